// round 1
// baseline (speedup 1.0000x reference)
#include <cuda_runtime.h>
#include <math.h>

#define DM 1024
#define NH 16
#define HD 64
#define MSL 5000
#define BB 2
#define SS 2048
#define MT (BB*SS)   // 4096 rows total

// Scratch (allocation-free rule: device globals)
__device__ float g_xpe[MT*DM];
__device__ float g_q[MT*DM];
__device__ float g_k[MT*DM];
__device__ float g_v[MT*DM];
__device__ float g_o[MT*DM];

// ---------------------------------------------------------------------------
// Kernel 1: x + alpha*sinusoid_pe + (1-alpha)*rel_emb  -> g_xpe
// Process one (sin,cos) pair per thread.
// ---------------------------------------------------------------------------
__global__ void pe_kernel(const float* __restrict__ x,
                          const float* __restrict__ rel,
                          const float* __restrict__ alphap) {
    int idx = blockIdx.x*blockDim.x + threadIdx.x;
    if (idx >= MT*(DM/2)) return;
    int m  = idx >> 9;        // / (DM/2)
    int pp = idx & 511;       // pair index
    int s  = m & (SS-1);      // position within sequence
    float a = alphap[0];
    // div = exp(2*pp * -ln(10000)/DM)
    float freq = __expf(-(float)(2*pp) * (9.210340371976184f/(float)DM));
    float ang = (float)s * freq;
    float sn, cs;
    sincosf(ang, &sn, &cs);   // accurate version: ang up to ~2047 rad
    const float* rr = rel + (size_t)(MSL - SS + s)*DM + 2*pp;
    float2 xv = *(const float2*)(x + (size_t)idx*2);
    float om = 1.0f - a;
    float2 o;
    o.x = xv.x + a*sn + om*rr[0];
    o.y = xv.y + a*cs + om*rr[1];
    *(float2*)(g_xpe + (size_t)idx*2) = o;
}

// ---------------------------------------------------------------------------
// fp32 SGEMM core: C[M=4096, N=1024] = A[M,K=1024] @ W[N,K]^T + bias
// 128x128 block tile, K-step 8, 256 threads, 8x8 microtile (split 4+4).
// ---------------------------------------------------------------------------
struct GemmFrag {
    float acc[8][8];
};

__device__ __forceinline__ void gemm_mainloop(const float* __restrict__ A,
                                              const float* __restrict__ W,
                                              int m0, int n0, int t,
                                              float (&acc)[8][8],
                                              float (*As)[132], float (*Bs)[132]) {
    const int lr = t >> 1;
    const int lc = (t & 1) * 4;
    const int ty = t >> 4, tx = t & 15;
    const float* Ap = A + (size_t)(m0 + lr)*DM + lc;
    const float* Wp = W + (size_t)(n0 + lr)*DM + lc;

    for (int k0 = 0; k0 < DM; k0 += 8) {
        float4 av = *(const float4*)(Ap + k0);
        float4 wv = *(const float4*)(Wp + k0);
        __syncthreads();
        As[lc+0][lr] = av.x; As[lc+1][lr] = av.y; As[lc+2][lr] = av.z; As[lc+3][lr] = av.w;
        Bs[lc+0][lr] = wv.x; Bs[lc+1][lr] = wv.y; Bs[lc+2][lr] = wv.z; Bs[lc+3][lr] = wv.w;
        __syncthreads();
        #pragma unroll
        for (int kk = 0; kk < 8; kk++) {
            float a[8], b[8];
            *(float4*)(a)   = *(const float4*)&As[kk][ty*4];
            *(float4*)(a+4) = *(const float4*)&As[kk][64 + ty*4];
            *(float4*)(b)   = *(const float4*)&Bs[kk][tx*4];
            *(float4*)(b+4) = *(const float4*)&Bs[kk][64 + tx*4];
            #pragma unroll
            for (int i = 0; i < 8; i++)
                #pragma unroll
                for (int j = 0; j < 8; j++)
                    acc[i][j] = fmaf(a[i], b[j], acc[i][j]);
        }
    }
}

// QKV projection: scatter store into [B, H, S, hd]
__global__ void __launch_bounds__(256) gemm_qkv(const float* __restrict__ W,
                                                const float* __restrict__ bias,
                                                int which) {
    float* out = (which == 0) ? g_q : (which == 1) ? g_k : g_v;
    __shared__ float As[8][132];
    __shared__ float Bs[8][132];
    const int t = threadIdx.x;
    const int m0 = blockIdx.y * 128, n0 = blockIdx.x * 128;
    const int ty = t >> 4, tx = t & 15;
    float acc[8][8];
    #pragma unroll
    for (int i = 0; i < 8; i++)
        #pragma unroll
        for (int j = 0; j < 8; j++) acc[i][j] = 0.f;

    gemm_mainloop(g_xpe, W, m0, n0, t, acc, As, Bs);

    #pragma unroll
    for (int i = 0; i < 8; i++) {
        int m = m0 + ((i < 4) ? (ty*4 + i) : (64 + ty*4 + i - 4));
        int bb = m >> 11;          // / SS
        int s  = m & (SS-1);
        #pragma unroll
        for (int jg = 0; jg < 2; jg++) {
            int n = n0 + jg*64 + tx*4;
            int h  = n >> 6;
            int dd = n & 63;
            float4 v;
            v.x = acc[i][jg*4+0] + bias[n+0];
            v.y = acc[i][jg*4+1] + bias[n+1];
            v.z = acc[i][jg*4+2] + bias[n+2];
            v.w = acc[i][jg*4+3] + bias[n+3];
            *(float4*)&out[(size_t)((bb*NH + h)*SS + s)*HD + dd] = v;
        }
    }
}

// Output projection: plain row-major store to d_out
__global__ void __launch_bounds__(256) gemm_out(const float* __restrict__ W,
                                                const float* __restrict__ bias,
                                                float* __restrict__ out) {
    __shared__ float As[8][132];
    __shared__ float Bs[8][132];
    const int t = threadIdx.x;
    const int m0 = blockIdx.y * 128, n0 = blockIdx.x * 128;
    const int ty = t >> 4, tx = t & 15;
    float acc[8][8];
    #pragma unroll
    for (int i = 0; i < 8; i++)
        #pragma unroll
        for (int j = 0; j < 8; j++) acc[i][j] = 0.f;

    gemm_mainloop(g_o, W, m0, n0, t, acc, As, Bs);

    #pragma unroll
    for (int i = 0; i < 8; i++) {
        int m = m0 + ((i < 4) ? (ty*4 + i) : (64 + ty*4 + i - 4));
        #pragma unroll
        for (int jg = 0; jg < 2; jg++) {
            int n = n0 + jg*64 + tx*4;
            float4 v;
            v.x = acc[i][jg*4+0] + bias[n+0];
            v.y = acc[i][jg*4+1] + bias[n+1];
            v.z = acc[i][jg*4+2] + bias[n+2];
            v.w = acc[i][jg*4+3] + bias[n+3];
            *(float4*)&out[(size_t)m*DM + n] = v;
        }
    }
}

// ---------------------------------------------------------------------------
// Flash attention (fp32, online softmax).
// Grid: (S/64, B*H). Block: 256 threads = 16(ty) x 16(tx).
// Per block: 64 queries. KV processed in tiles of 32.
// Thread owns S rows ty*4..+3, S cols tx*2..+1 ; O rows ty*4..+3, cols tx*4..+3.
// scale = 1/sqrt(D_MODEL) = 1/32 (note: NOT 1/sqrt(head_dim)).
// ---------------------------------------------------------------------------
__global__ void __launch_bounds__(256) flash_kernel() {
    const int bh = blockIdx.y;
    const int q0 = blockIdx.x * 64;
    const float* Q = g_q + (size_t)bh * SS * HD;
    const float* K = g_k + (size_t)bh * SS * HD;
    const float* V = g_v + (size_t)bh * SS * HD;

    __shared__ float Qt[HD][64];   // [d][q]  (transposed)
    __shared__ float Kt[HD][32];   // [d][kv] (transposed)
    __shared__ float Vs[32][HD];   // [kv][d]
    __shared__ float Ps[64][36];   // [q][kv], padded stride 36 (16B-aligned rows)

    const int t = threadIdx.x;
    const int ty = t >> 4, tx = t & 15;

    // Load Q tile transposed: lane owns one q-row, 16 d-values -> conflict-free stores
    {
        int q  = t & 63;
        int d0 = (t >> 6) * 16;
        const float4* src = (const float4*)&Q[(size_t)(q0 + q)*HD + d0];
        #pragma unroll
        for (int u = 0; u < 4; u++) {
            float4 v = src[u];
            Qt[d0 + u*4 + 0][q] = v.x;
            Qt[d0 + u*4 + 1][q] = v.y;
            Qt[d0 + u*4 + 2][q] = v.z;
            Qt[d0 + u*4 + 3][q] = v.w;
        }
    }

    float acc[4][4];
    float mprev[4], l[4];
    #pragma unroll
    for (int i = 0; i < 4; i++) {
        mprev[i] = -1e30f; l[i] = 0.f;
        #pragma unroll
        for (int j = 0; j < 4; j++) acc[i][j] = 0.f;
    }
    __syncthreads();

    const int kvlane = t & 31;
    const int kd0    = (t >> 5) * 8;

    for (int kv0 = 0; kv0 < SS; kv0 += 32) {
        // K tile transposed (lane owns one kv-row, 8 d-values), V tile direct copy
        {
            const float4* ks = (const float4*)&K[(size_t)(kv0 + kvlane)*HD + kd0];
            float4 ka = ks[0], kb = ks[1];
            Kt[kd0+0][kvlane] = ka.x; Kt[kd0+1][kvlane] = ka.y;
            Kt[kd0+2][kvlane] = ka.z; Kt[kd0+3][kvlane] = ka.w;
            Kt[kd0+4][kvlane] = kb.x; Kt[kd0+5][kvlane] = kb.y;
            Kt[kd0+6][kvlane] = kb.z; Kt[kd0+7][kvlane] = kb.w;
            #pragma unroll
            for (int i = 0; i < 2; i++) {
                int idx = t + i*256;
                int row = idx >> 4, c4 = (idx & 15) * 4;
                *(float4*)&Vs[row][c4] = *(const float4*)&V[(size_t)(kv0 + row)*HD + c4];
            }
        }
        __syncthreads();

        // S = Q K^T (4x2 per thread)
        float sc[4][2];
        #pragma unroll
        for (int i = 0; i < 4; i++) { sc[i][0] = 0.f; sc[i][1] = 0.f; }
        #pragma unroll 4
        for (int d = 0; d < HD; d++) {
            float a4[4];
            *(float4*)a4 = *(const float4*)&Qt[d][ty*4];
            float2 b2 = *(const float2*)&Kt[d][tx*2];
            #pragma unroll
            for (int i = 0; i < 4; i++) {
                sc[i][0] = fmaf(a4[i], b2.x, sc[i][0]);
                sc[i][1] = fmaf(a4[i], b2.y, sc[i][1]);
            }
        }

        // Online softmax stats; row groups = 16 consecutive lanes (xor 8,4,2,1 stays in group)
        const float scale = 0.03125f;  // 1/sqrt(1024)
        float mnew[4], rs[4];
        #pragma unroll
        for (int i = 0; i < 4; i++) {
            sc[i][0] *= scale; sc[i][1] *= scale;
            float ml = fmaxf(sc[i][0], sc[i][1]);
            #pragma unroll
            for (int off = 8; off > 0; off >>= 1)
                ml = fmaxf(ml, __shfl_xor_sync(0xffffffffu, ml, off));
            float mn = fmaxf(mprev[i], ml);
            mnew[i] = mn;
            float p0 = __expf(sc[i][0] - mn);
            float p1 = __expf(sc[i][1] - mn);
            Ps[ty*4 + i][tx*2 + 0] = p0;
            Ps[ty*4 + i][tx*2 + 1] = p1;
            float rl = p0 + p1;
            #pragma unroll
            for (int off = 8; off > 0; off >>= 1)
                rl += __shfl_xor_sync(0xffffffffu, rl, off);
            rs[i] = rl;
        }
        #pragma unroll
        for (int i = 0; i < 4; i++) {
            float al = __expf(mprev[i] - mnew[i]);
            l[i] = l[i]*al + rs[i];
            mprev[i] = mnew[i];
            #pragma unroll
            for (int j = 0; j < 4; j++) acc[i][j] *= al;
        }
        __syncthreads();

        // O += P @ V (j blocked by 4, float4 smem reads)
        #pragma unroll
        for (int j0 = 0; j0 < 32; j0 += 4) {
            float pv[4][4];
            #pragma unroll
            for (int i = 0; i < 4; i++)
                *(float4*)pv[i] = *(const float4*)&Ps[ty*4 + i][j0];
            #pragma unroll
            for (int jj = 0; jj < 4; jj++) {
                float4 vv = *(const float4*)&Vs[j0 + jj][tx*4];
                #pragma unroll
                for (int i = 0; i < 4; i++) {
                    acc[i][0] = fmaf(pv[i][jj], vv.x, acc[i][0]);
                    acc[i][1] = fmaf(pv[i][jj], vv.y, acc[i][1]);
                    acc[i][2] = fmaf(pv[i][jj], vv.z, acc[i][2]);
                    acc[i][3] = fmaf(pv[i][jj], vv.w, acc[i][3]);
                }
            }
        }
        __syncthreads();
    }

    // Normalize and write to [B, S, D] layout for the output GEMM
    const int bb = bh >> 4, h = bh & 15;
    #pragma unroll
    for (int i = 0; i < 4; i++) {
        float inv = 1.0f / l[i];
        int srow = q0 + ty*4 + i;
        float4 v;
        v.x = acc[i][0]*inv; v.y = acc[i][1]*inv;
        v.z = acc[i][2]*inv; v.w = acc[i][3]*inv;
        *(float4*)&g_o[(size_t)(bb*SS + srow)*DM + h*HD + tx*4] = v;
    }
}

// ---------------------------------------------------------------------------
extern "C" void kernel_launch(void* const* d_in, const int* in_sizes, int n_in,
                              void* d_out, int out_size) {
    const float* x     = (const float*)d_in[0];
    const float* rel   = (const float*)d_in[1];
    const float* alpha = (const float*)d_in[2];
    const float* Wq    = (const float*)d_in[3];
    const float* bq    = (const float*)d_in[4];
    const float* Wk    = (const float*)d_in[5];
    const float* bk    = (const float*)d_in[6];
    const float* Wv    = (const float*)d_in[7];
    const float* bv    = (const float*)d_in[8];
    const float* Wo    = (const float*)d_in[9];
    const float* bo    = (const float*)d_in[10];
    float* out = (float*)d_out;

    pe_kernel<<<(MT*(DM/2) + 255)/256, 256>>>(x, rel, alpha);

    dim3 gg(DM/128, MT/128);   // (8, 32)
    gemm_qkv<<<gg, 256>>>(Wq, bq, 0);
    gemm_qkv<<<gg, 256>>>(Wk, bk, 1);
    gemm_qkv<<<gg, 256>>>(Wv, bv, 2);

    flash_kernel<<<dim3(SS/64, BB*NH), 256>>>();

    gemm_out<<<gg, 256>>>(Wo, bo, out);
}

// round 4
// speedup vs baseline: 1.2552x; 1.2552x over previous
#include <cuda_runtime.h>
#include <cuda_bf16.h>
#include <math.h>
#include <stdint.h>

#define DM 1024
#define NH 16
#define HD 64
#define MSL 5000
#define BB 2
#define SS 2048
#define MT (BB*SS)   // 4096 rows total

// Scratch (allocation-free rule: device globals)
__device__ float g_xpe[MT*DM];
__device__ float g_q[MT*DM];
__device__ float g_k[MT*DM];
__device__ float g_v[MT*DM];
__device__ float g_o[MT*DM];
// split-bf16 operands for tensor-core GEMMs
__device__ __nv_bfloat16 g_ah[MT*DM];
__device__ __nv_bfloat16 g_al[MT*DM];
__device__ __nv_bfloat16 g_wh[DM*DM];
__device__ __nv_bfloat16 g_wl[DM*DM];

// ---------------------------------------------------------------------------
// helpers
// ---------------------------------------------------------------------------
__device__ __forceinline__ uint32_t smem_u32(const void* p) {
    uint32_t a;
    asm("{ .reg .u64 t; cvta.to.shared.u64 t, %1; cvt.u32.u64 %0, t; }" : "=r"(a) : "l"(p));
    return a;
}

#define CP16(dst, src) \
    asm volatile("cp.async.cg.shared.global [%0], [%1], 16;" :: "r"(dst), "l"(src))
#define CP_COMMIT()  asm volatile("cp.async.commit_group;" ::: "memory")
#define CP_WAIT(n)   asm volatile("cp.async.wait_group %0;" :: "n"(n) : "memory")

#define LDSM4(r, addr) \
    asm volatile("ldmatrix.sync.aligned.m8n8.x4.shared.b16 {%0,%1,%2,%3}, [%4];" \
        : "=r"((r)[0]), "=r"((r)[1]), "=r"((r)[2]), "=r"((r)[3]) : "r"(addr))

#define MMA16816(d, a, b0v, b1v) \
    asm volatile("mma.sync.aligned.m16n8k16.row.col.f32.bf16.bf16.f32 " \
        "{%0,%1,%2,%3}, {%4,%5,%6,%7}, {%8,%9}, {%0,%1,%2,%3};" \
        : "+f"((d)[0]), "+f"((d)[1]), "+f"((d)[2]), "+f"((d)[3]) \
        : "r"((a)[0]), "r"((a)[1]), "r"((a)[2]), "r"((a)[3]), "r"(b0v), "r"(b1v))

// ---------------------------------------------------------------------------
// Kernel 1: x + alpha*sinusoid_pe + (1-alpha)*rel_emb  -> g_xpe
// ---------------------------------------------------------------------------
__global__ void pe_kernel(const float* __restrict__ x,
                          const float* __restrict__ rel,
                          const float* __restrict__ alphap) {
    int idx = blockIdx.x*blockDim.x + threadIdx.x;
    if (idx >= MT*(DM/2)) return;
    int m  = idx >> 9;
    int pp = idx & 511;
    int s  = m & (SS-1);
    float a = alphap[0];
    float freq = __expf(-(float)(2*pp) * (9.210340371976184f/(float)DM));
    float ang = (float)s * freq;
    float sn, cs;
    sincosf(ang, &sn, &cs);
    const float* rr = rel + (size_t)(MSL - SS + s)*DM + 2*pp;
    float2 xv = *(const float2*)(x + (size_t)idx*2);
    float om = 1.0f - a;
    float2 o;
    o.x = xv.x + a*sn + om*rr[0];
    o.y = xv.y + a*cs + om*rr[1];
    *(float2*)(g_xpe + (size_t)idx*2) = o;
}

// ---------------------------------------------------------------------------
// Kernel 2: fp32 -> (hi, lo) bf16 split.  v ~= hi + lo to ~16 mantissa bits.
// ---------------------------------------------------------------------------
__global__ void split_kernel(const float* __restrict__ src,
                             __nv_bfloat16* __restrict__ hi,
                             __nv_bfloat16* __restrict__ lo, int n4) {
    int i = blockIdx.x*blockDim.x + threadIdx.x;
    if (i >= n4) return;
    float4 v = ((const float4*)src)[i];
    __nv_bfloat16 h0 = __float2bfloat16(v.x);
    __nv_bfloat16 h1 = __float2bfloat16(v.y);
    __nv_bfloat16 h2 = __float2bfloat16(v.z);
    __nv_bfloat16 h3 = __float2bfloat16(v.w);
    __nv_bfloat16 l0 = __float2bfloat16(v.x - __bfloat162float(h0));
    __nv_bfloat16 l1 = __float2bfloat16(v.y - __bfloat162float(h1));
    __nv_bfloat16 l2 = __float2bfloat16(v.z - __bfloat162float(h2));
    __nv_bfloat16 l3 = __float2bfloat16(v.w - __bfloat162float(h3));
    __nv_bfloat162* hp = (__nv_bfloat162*)(hi + (size_t)i*4);
    __nv_bfloat162* lp = (__nv_bfloat162*)(lo + (size_t)i*4);
    hp[0] = __nv_bfloat162(h0, h1); hp[1] = __nv_bfloat162(h2, h3);
    lp[0] = __nv_bfloat162(l0, l1); lp[1] = __nv_bfloat162(l2, l3);
}

// ---------------------------------------------------------------------------
// mma.sync split-bf16 GEMM: C[4096,1024] = A @ W^T + bias
//   C = Ah Wh^T + Ah Wl^T + Al Wh^T, fp32 accumulators.
// Block 128x128, 256 threads (8 warps, 2x4), warp tile 64x32.
// K-chunk 32, double-buffered cp.async staging. Smem rows 32 bf16 padded to
// 80B stride -> conflict-free ldmatrix (banks 20r mod 32 all-distinct r<8).
// mode 0/1/2: scatter into g_q/g_k/g_v [B,H,S,hd]; mode 3: row-major outp.
// ---------------------------------------------------------------------------
#define RS   80                      // smem row stride bytes
#define ASZ  (128*RS)                // 10240 per array
#define BUFSZ (4*ASZ)                // AH AL BH BL
#define GEMM_SMEM (2*BUFSZ)          // 81920

__global__ void __launch_bounds__(256, 1) gemm_mma(const __nv_bfloat16* __restrict__ Ah,
                                                   const __nv_bfloat16* __restrict__ Al,
                                                   const float* __restrict__ bias,
                                                   float* __restrict__ outp,
                                                   int mode) {
    extern __shared__ char smem[];
    const uint32_t sb = smem_u32(smem);
    const int t  = threadIdx.x;
    const int m0 = blockIdx.y * 128;
    const int n0 = blockIdx.x * 128;

    const int wid = t >> 5, l = t & 31;
    const int warpM = wid & 1;        // 2 warps in M
    const int warpN = wid >> 1;       // 4 warps in N
    const int q  = l >> 3, lr = l & 7;

    const __nv_bfloat16* __restrict__ Bh = g_wh;
    const __nv_bfloat16* __restrict__ Bl = g_wl;

    // per-thread staging coords: row = t>>1, chunk pair (t&1)*2
    const int ldrow = t >> 1;
    const int ldc   = (t & 1) * 2;
    const size_t a_row_off = (size_t)(m0 + ldrow) * DM;
    const size_t b_row_off = (size_t)(n0 + ldrow) * DM;
    const uint32_t st_off  = (uint32_t)ldrow * RS + (uint32_t)ldc * 16;

    float acc[16][4];
    #pragma unroll
    for (int i = 0; i < 16; i++)
        #pragma unroll
        for (int j = 0; j < 4; j++) acc[i][j] = 0.f;

    // ldmatrix lane base addresses (relative to array base)
    const uint32_t a_lane = (uint32_t)(warpM*64 + (q & 1)*8 + lr) * RS + (uint32_t)(q >> 1) * 16;
    const uint32_t b_lane = (uint32_t)(warpN*32 + (q >> 1)*8 + lr) * RS + (uint32_t)(q & 1) * 16;

    // prologue: stage chunk 0 into buffer 0
    {
        const int k0 = 0;
        uint32_t d = sb + st_off;
        CP16(d + 0*ASZ +  0, Ah + a_row_off + k0 + ldc*8);
        CP16(d + 0*ASZ + 16, Ah + a_row_off + k0 + ldc*8 + 8);
        CP16(d + 1*ASZ +  0, Al + a_row_off + k0 + ldc*8);
        CP16(d + 1*ASZ + 16, Al + a_row_off + k0 + ldc*8 + 8);
        CP16(d + 2*ASZ +  0, Bh + b_row_off + k0 + ldc*8);
        CP16(d + 2*ASZ + 16, Bh + b_row_off + k0 + ldc*8 + 8);
        CP16(d + 3*ASZ +  0, Bl + b_row_off + k0 + ldc*8);
        CP16(d + 3*ASZ + 16, Bl + b_row_off + k0 + ldc*8 + 8);
        CP_COMMIT();
    }

    for (int ch = 0; ch < DM/32; ch++) {
        if (ch < DM/32 - 1) {
            const int k0 = (ch + 1) * 32;
            uint32_t d = sb + ((ch + 1) & 1) * BUFSZ + st_off;
            CP16(d + 0*ASZ +  0, Ah + a_row_off + k0 + ldc*8);
            CP16(d + 0*ASZ + 16, Ah + a_row_off + k0 + ldc*8 + 8);
            CP16(d + 1*ASZ +  0, Al + a_row_off + k0 + ldc*8);
            CP16(d + 1*ASZ + 16, Al + a_row_off + k0 + ldc*8 + 8);
            CP16(d + 2*ASZ +  0, Bh + b_row_off + k0 + ldc*8);
            CP16(d + 2*ASZ + 16, Bh + b_row_off + k0 + ldc*8 + 8);
            CP16(d + 3*ASZ +  0, Bl + b_row_off + k0 + ldc*8);
            CP16(d + 3*ASZ + 16, Bl + b_row_off + k0 + ldc*8 + 8);
            CP_COMMIT();
            CP_WAIT(1);
        } else {
            CP_WAIT(0);
        }
        __syncthreads();

        const uint32_t buf = sb + (ch & 1) * BUFSZ;
        #pragma unroll
        for (int ks = 0; ks < 32; ks += 16) {
            const uint32_t kadd = (uint32_t)ks * 2;  // (ks/8)*16 bytes
            uint32_t ah[4][4], alr[4][4];
            #pragma unroll
            for (int mt = 0; mt < 4; mt++) {
                uint32_t ao = a_lane + (uint32_t)mt * 16 * RS + kadd;
                LDSM4(ah[mt],  buf + 0*ASZ + ao);
                LDSM4(alr[mt], buf + 1*ASZ + ao);
            }
            uint32_t bh[2][4], bl[2][4];
            #pragma unroll
            for (int np = 0; np < 2; np++) {
                uint32_t bo = b_lane + (uint32_t)np * 16 * RS + kadd;
                LDSM4(bh[np], buf + 2*ASZ + bo);
                LDSM4(bl[np], buf + 3*ASZ + bo);
            }
            #pragma unroll
            for (int mt = 0; mt < 4; mt++) {
                #pragma unroll
                for (int nt = 0; nt < 4; nt++) {
                    const int np = nt >> 1, h = (nt & 1) * 2;
                    MMA16816(acc[mt*4+nt], ah[mt],  bh[np][h], bh[np][h+1]);
                    MMA16816(acc[mt*4+nt], ah[mt],  bl[np][h], bl[np][h+1]);
                    MMA16816(acc[mt*4+nt], alr[mt], bh[np][h], bh[np][h+1]);
                }
            }
        }
        __syncthreads();
    }

    // epilogue
    float* outg = (mode == 0) ? g_q : (mode == 1) ? g_k : (mode == 2) ? g_v : outp;
    #pragma unroll
    for (int nt = 0; nt < 4; nt++) {
        const int n = n0 + warpN*32 + nt*8 + (l & 3)*2;
        const float bx = bias[n], by = bias[n+1];
        #pragma unroll
        for (int mt = 0; mt < 4; mt++) {
            const float* d = acc[mt*4 + nt];
            #pragma unroll
            for (int half = 0; half < 2; half++) {
                const int m = m0 + warpM*64 + mt*16 + (l >> 2) + half*8;
                float2 v;
                v.x = d[half*2 + 0] + bx;
                v.y = d[half*2 + 1] + by;
                if (mode == 3) {
                    *(float2*)&outg[(size_t)m*DM + n] = v;
                } else {
                    const int bb = m >> 11, s = m & (SS-1);
                    const int hh = n >> 6, dd = n & 63;
                    *(float2*)&outg[(size_t)((bb*NH + hh)*SS + s)*HD + dd] = v;
                }
            }
        }
    }
}

// ---------------------------------------------------------------------------
// Flash attention (fp32, online softmax) — unchanged.
// ---------------------------------------------------------------------------
__global__ void __launch_bounds__(256) flash_kernel() {
    const int bh = blockIdx.y;
    const int q0 = blockIdx.x * 64;
    const float* Q = g_q + (size_t)bh * SS * HD;
    const float* K = g_k + (size_t)bh * SS * HD;
    const float* V = g_v + (size_t)bh * SS * HD;

    __shared__ float Qt[HD][64];
    __shared__ float Kt[HD][32];
    __shared__ float Vs[32][HD];
    __shared__ float Ps[64][36];

    const int t = threadIdx.x;
    const int ty = t >> 4, tx = t & 15;

    {
        int q  = t & 63;
        int d0 = (t >> 6) * 16;
        const float4* src = (const float4*)&Q[(size_t)(q0 + q)*HD + d0];
        #pragma unroll
        for (int u = 0; u < 4; u++) {
            float4 v = src[u];
            Qt[d0 + u*4 + 0][q] = v.x;
            Qt[d0 + u*4 + 1][q] = v.y;
            Qt[d0 + u*4 + 2][q] = v.z;
            Qt[d0 + u*4 + 3][q] = v.w;
        }
    }

    float acc[4][4];
    float mprev[4], l[4];
    #pragma unroll
    for (int i = 0; i < 4; i++) {
        mprev[i] = -1e30f; l[i] = 0.f;
        #pragma unroll
        for (int j = 0; j < 4; j++) acc[i][j] = 0.f;
    }
    __syncthreads();

    const int kvlane = t & 31;
    const int kd0    = (t >> 5) * 8;

    for (int kv0 = 0; kv0 < SS; kv0 += 32) {
        {
            const float4* ks = (const float4*)&K[(size_t)(kv0 + kvlane)*HD + kd0];
            float4 ka = ks[0], kb = ks[1];
            Kt[kd0+0][kvlane] = ka.x; Kt[kd0+1][kvlane] = ka.y;
            Kt[kd0+2][kvlane] = ka.z; Kt[kd0+3][kvlane] = ka.w;
            Kt[kd0+4][kvlane] = kb.x; Kt[kd0+5][kvlane] = kb.y;
            Kt[kd0+6][kvlane] = kb.z; Kt[kd0+7][kvlane] = kb.w;
            #pragma unroll
            for (int i = 0; i < 2; i++) {
                int idx = t + i*256;
                int row = idx >> 4, c4 = (idx & 15) * 4;
                *(float4*)&Vs[row][c4] = *(const float4*)&V[(size_t)(kv0 + row)*HD + c4];
            }
        }
        __syncthreads();

        float sc[4][2];
        #pragma unroll
        for (int i = 0; i < 4; i++) { sc[i][0] = 0.f; sc[i][1] = 0.f; }
        #pragma unroll 4
        for (int d = 0; d < HD; d++) {
            float a4[4];
            *(float4*)a4 = *(const float4*)&Qt[d][ty*4];
            float2 b2 = *(const float2*)&Kt[d][tx*2];
            #pragma unroll
            for (int i = 0; i < 4; i++) {
                sc[i][0] = fmaf(a4[i], b2.x, sc[i][0]);
                sc[i][1] = fmaf(a4[i], b2.y, sc[i][1]);
            }
        }

        const float scale = 0.03125f;
        float mnew[4], rs[4];
        #pragma unroll
        for (int i = 0; i < 4; i++) {
            sc[i][0] *= scale; sc[i][1] *= scale;
            float ml = fmaxf(sc[i][0], sc[i][1]);
            #pragma unroll
            for (int off = 8; off > 0; off >>= 1)
                ml = fmaxf(ml, __shfl_xor_sync(0xffffffffu, ml, off));
            float mn = fmaxf(mprev[i], ml);
            mnew[i] = mn;
            float p0 = __expf(sc[i][0] - mn);
            float p1 = __expf(sc[i][1] - mn);
            Ps[ty*4 + i][tx*2 + 0] = p0;
            Ps[ty*4 + i][tx*2 + 1] = p1;
            float rl = p0 + p1;
            #pragma unroll
            for (int off = 8; off > 0; off >>= 1)
                rl += __shfl_xor_sync(0xffffffffu, rl, off);
            rs[i] = rl;
        }
        #pragma unroll
        for (int i = 0; i < 4; i++) {
            float al = __expf(mprev[i] - mnew[i]);
            l[i] = l[i]*al + rs[i];
            mprev[i] = mnew[i];
            #pragma unroll
            for (int j = 0; j < 4; j++) acc[i][j] *= al;
        }
        __syncthreads();

        #pragma unroll
        for (int j0 = 0; j0 < 32; j0 += 4) {
            float pv[4][4];
            #pragma unroll
            for (int i = 0; i < 4; i++)
                *(float4*)pv[i] = *(const float4*)&Ps[ty*4 + i][j0];
            #pragma unroll
            for (int jj = 0; jj < 4; jj++) {
                float4 vv = *(const float4*)&Vs[j0 + jj][tx*4];
                #pragma unroll
                for (int i = 0; i < 4; i++) {
                    acc[i][0] = fmaf(pv[i][jj], vv.x, acc[i][0]);
                    acc[i][1] = fmaf(pv[i][jj], vv.y, acc[i][1]);
                    acc[i][2] = fmaf(pv[i][jj], vv.z, acc[i][2]);
                    acc[i][3] = fmaf(pv[i][jj], vv.w, acc[i][3]);
                }
            }
        }
        __syncthreads();
    }

    const int bb = bh >> 4, h = bh & 15;
    #pragma unroll
    for (int i = 0; i < 4; i++) {
        float inv = 1.0f / l[i];
        int srow = q0 + ty*4 + i;
        float4 v;
        v.x = acc[i][0]*inv; v.y = acc[i][1]*inv;
        v.z = acc[i][2]*inv; v.w = acc[i][3]*inv;
        *(float4*)&g_o[(size_t)(bb*SS + srow)*DM + h*HD + tx*4] = v;
    }
}

// ---------------------------------------------------------------------------
extern "C" void kernel_launch(void* const* d_in, const int* in_sizes, int n_in,
                              void* d_out, int out_size) {
    const float* x     = (const float*)d_in[0];
    const float* rel   = (const float*)d_in[1];
    const float* alpha = (const float*)d_in[2];
    const float* Wq    = (const float*)d_in[3];
    const float* bq    = (const float*)d_in[4];
    const float* Wk    = (const float*)d_in[5];
    const float* bk    = (const float*)d_in[6];
    const float* Wv    = (const float*)d_in[7];
    const float* bv    = (const float*)d_in[8];
    const float* Wo    = (const float*)d_in[9];
    const float* bo    = (const float*)d_in[10];
    float* out = (float*)d_out;

    cudaFuncSetAttribute(gemm_mma, cudaFuncAttributeMaxDynamicSharedMemorySize, GEMM_SMEM);

    __nv_bfloat16 *ah, *al, *wh, *wl;
    float *xpe, *go;
    cudaGetSymbolAddress((void**)&ah,  g_ah);
    cudaGetSymbolAddress((void**)&al,  g_al);
    cudaGetSymbolAddress((void**)&wh,  g_wh);
    cudaGetSymbolAddress((void**)&wl,  g_wl);
    cudaGetSymbolAddress((void**)&xpe, g_xpe);
    cudaGetSymbolAddress((void**)&go,  g_o);

    pe_kernel<<<(MT*(DM/2) + 255)/256, 256>>>(x, rel, alpha);

    const int nA4 = MT*DM/4, nW4 = DM*DM/4;
    split_kernel<<<(nA4 + 255)/256, 256>>>(xpe, ah, al, nA4);

    dim3 gg(DM/128, MT/128);   // (8, 32)
    split_kernel<<<(nW4 + 255)/256, 256>>>(Wq, wh, wl, nW4);
    gemm_mma<<<gg, 256, GEMM_SMEM>>>(ah, al, bq, nullptr, 0);
    split_kernel<<<(nW4 + 255)/256, 256>>>(Wk, wh, wl, nW4);
    gemm_mma<<<gg, 256, GEMM_SMEM>>>(ah, al, bk, nullptr, 1);
    split_kernel<<<(nW4 + 255)/256, 256>>>(Wv, wh, wl, nW4);
    gemm_mma<<<gg, 256, GEMM_SMEM>>>(ah, al, bv, nullptr, 2);

    flash_kernel<<<dim3(SS/64, BB*NH), 256>>>();

    split_kernel<<<(nA4 + 255)/256, 256>>>(go, ah, al, nA4);
    split_kernel<<<(nW4 + 255)/256, 256>>>(Wo, wh, wl, nW4);
    gemm_mma<<<gg, 256, GEMM_SMEM>>>(ah, al, bo, out, 3);
}

// round 5
// speedup vs baseline: 2.6563x; 2.1162x over previous
#include <cuda_runtime.h>
#include <cuda_bf16.h>
#include <math.h>
#include <stdint.h>

#define DM 1024
#define NH 16
#define HD 64
#define MSL 5000
#define BB 2
#define SS 2048
#define MT (BB*SS)   // 4096 rows total

// Scratch (allocation-free rule: device globals)
__device__ float g_xpe[MT*DM];
__device__ __nv_bfloat16 g_ah[MT*DM];   // GEMM A operand hi (xpe-split, later o-split)
__device__ __nv_bfloat16 g_al[MT*DM];   // GEMM A operand lo
__device__ __nv_bfloat16 g_wh[DM*DM];
__device__ __nv_bfloat16 g_wl[DM*DM];
// split-bf16 Q/K/V in [B,H,S,hd] (Q pre-scaled by 1/32)
__device__ __nv_bfloat16 g_qh[MT*DM];
__device__ __nv_bfloat16 g_ql[MT*DM];
__device__ __nv_bfloat16 g_kh[MT*DM];
__device__ __nv_bfloat16 g_kl[MT*DM];
__device__ __nv_bfloat16 g_vh[MT*DM];
__device__ __nv_bfloat16 g_vl[MT*DM];

// ---------------------------------------------------------------------------
// helpers
// ---------------------------------------------------------------------------
__device__ __forceinline__ uint32_t smem_u32(const void* p) {
    uint32_t a;
    asm("{ .reg .u64 t; cvta.to.shared.u64 t, %1; cvt.u32.u64 %0, t; }" : "=r"(a) : "l"(p));
    return a;
}

#define CP16(dst, src) \
    asm volatile("cp.async.cg.shared.global [%0], [%1], 16;" :: "r"(dst), "l"(src))
#define CP_COMMIT()  asm volatile("cp.async.commit_group;" ::: "memory")
#define CP_WAIT(n)   asm volatile("cp.async.wait_group %0;" :: "n"(n) : "memory")

#define LDSM4(r, addr) \
    asm volatile("ldmatrix.sync.aligned.m8n8.x4.shared.b16 {%0,%1,%2,%3}, [%4];" \
        : "=r"((r)[0]), "=r"((r)[1]), "=r"((r)[2]), "=r"((r)[3]) : "r"(addr))

#define LDSM4T(r, addr) \
    asm volatile("ldmatrix.sync.aligned.m8n8.x4.trans.shared.b16 {%0,%1,%2,%3}, [%4];" \
        : "=r"((r)[0]), "=r"((r)[1]), "=r"((r)[2]), "=r"((r)[3]) : "r"(addr))

#define MMA16816(d, a, b0v, b1v) \
    asm volatile("mma.sync.aligned.m16n8k16.row.col.f32.bf16.bf16.f32 " \
        "{%0,%1,%2,%3}, {%4,%5,%6,%7}, {%8,%9}, {%0,%1,%2,%3};" \
        : "+f"((d)[0]), "+f"((d)[1]), "+f"((d)[2]), "+f"((d)[3]) \
        : "r"((a)[0]), "r"((a)[1]), "r"((a)[2]), "r"((a)[3]), "r"(b0v), "r"(b1v))

// pack two fp32 into bf16x2: low half = lo, high half = hi
__device__ __forceinline__ uint32_t pack_bf(float hi, float lo) {
    uint32_t d;
    asm("cvt.rn.bf16x2.f32 %0, %1, %2;" : "=r"(d) : "f"(hi), "f"(lo));
    return d;
}
__device__ __forceinline__ float bf_round(float v) {
    return __bfloat162float(__float2bfloat16(v));
}

// ---------------------------------------------------------------------------
// Kernel 1: x + alpha*sinusoid_pe + (1-alpha)*rel_emb  -> g_xpe
// ---------------------------------------------------------------------------
__global__ void pe_kernel(const float* __restrict__ x,
                          const float* __restrict__ rel,
                          const float* __restrict__ alphap) {
    int idx = blockIdx.x*blockDim.x + threadIdx.x;
    if (idx >= MT*(DM/2)) return;
    int m  = idx >> 9;
    int pp = idx & 511;
    int s  = m & (SS-1);
    float a = alphap[0];
    float freq = __expf(-(float)(2*pp) * (9.210340371976184f/(float)DM));
    float ang = (float)s * freq;
    float sn, cs;
    sincosf(ang, &sn, &cs);
    const float* rr = rel + (size_t)(MSL - SS + s)*DM + 2*pp;
    float2 xv = *(const float2*)(x + (size_t)idx*2);
    float om = 1.0f - a;
    float2 o;
    o.x = xv.x + a*sn + om*rr[0];
    o.y = xv.y + a*cs + om*rr[1];
    *(float2*)(g_xpe + (size_t)idx*2) = o;
}

// ---------------------------------------------------------------------------
// Kernel 2: fp32 -> (hi, lo) bf16 split.
// ---------------------------------------------------------------------------
__global__ void split_kernel(const float* __restrict__ src,
                             __nv_bfloat16* __restrict__ hi,
                             __nv_bfloat16* __restrict__ lo, int n4) {
    int i = blockIdx.x*blockDim.x + threadIdx.x;
    if (i >= n4) return;
    float4 v = ((const float4*)src)[i];
    __nv_bfloat16 h0 = __float2bfloat16(v.x);
    __nv_bfloat16 h1 = __float2bfloat16(v.y);
    __nv_bfloat16 h2 = __float2bfloat16(v.z);
    __nv_bfloat16 h3 = __float2bfloat16(v.w);
    __nv_bfloat16 l0 = __float2bfloat16(v.x - __bfloat162float(h0));
    __nv_bfloat16 l1 = __float2bfloat16(v.y - __bfloat162float(h1));
    __nv_bfloat16 l2 = __float2bfloat16(v.z - __bfloat162float(h2));
    __nv_bfloat16 l3 = __float2bfloat16(v.w - __bfloat162float(h3));
    __nv_bfloat162* hp = (__nv_bfloat162*)(hi + (size_t)i*4);
    __nv_bfloat162* lp = (__nv_bfloat162*)(lo + (size_t)i*4);
    hp[0] = __nv_bfloat162(h0, h1); hp[1] = __nv_bfloat162(h2, h3);
    lp[0] = __nv_bfloat162(l0, l1); lp[1] = __nv_bfloat162(l2, l3);
}

// ---------------------------------------------------------------------------
// mma.sync split-bf16 GEMM: C[4096,1024] = A @ W^T + bias (then * ascale)
// Block 128x128, 256 threads, warp tile 64x32, K-chunk 32, 2-stage cp.async.
// mode 0/1/2: split-bf16 scatter into g_{q,k,v}{h,l} [B,H,S,hd].
// mode 3: fp32 row-major outp.
// ---------------------------------------------------------------------------
#define RS   80                      // smem row stride bytes
#define ASZ  (128*RS)                // 10240 per array
#define BUFSZ (4*ASZ)                // AH AL BH BL
#define GEMM_SMEM (2*BUFSZ)          // 81920

__global__ void __launch_bounds__(256, 1) gemm_mma(const __nv_bfloat16* __restrict__ Ah,
                                                   const __nv_bfloat16* __restrict__ Al,
                                                   const float* __restrict__ bias,
                                                   float* __restrict__ outp,
                                                   float ascale,
                                                   int mode) {
    extern __shared__ char smem[];
    const uint32_t sb = smem_u32(smem);
    const int t  = threadIdx.x;
    const int m0 = blockIdx.y * 128;
    const int n0 = blockIdx.x * 128;

    const int wid = t >> 5, l = t & 31;
    const int warpM = wid & 1;
    const int warpN = wid >> 1;
    const int q  = l >> 3, lr = l & 7;

    const __nv_bfloat16* __restrict__ Bh = g_wh;
    const __nv_bfloat16* __restrict__ Bl = g_wl;

    const int ldrow = t >> 1;
    const int ldc   = (t & 1) * 2;
    const size_t a_row_off = (size_t)(m0 + ldrow) * DM;
    const size_t b_row_off = (size_t)(n0 + ldrow) * DM;
    const uint32_t st_off  = (uint32_t)ldrow * RS + (uint32_t)ldc * 16;

    float acc[16][4];
    #pragma unroll
    for (int i = 0; i < 16; i++)
        #pragma unroll
        for (int j = 0; j < 4; j++) acc[i][j] = 0.f;

    const uint32_t a_lane = (uint32_t)(warpM*64 + (q & 1)*8 + lr) * RS + (uint32_t)(q >> 1) * 16;
    const uint32_t b_lane = (uint32_t)(warpN*32 + (q >> 1)*8 + lr) * RS + (uint32_t)(q & 1) * 16;

    // prologue: stage chunk 0 into buffer 0
    {
        uint32_t d = sb + st_off;
        CP16(d + 0*ASZ +  0, Ah + a_row_off + ldc*8);
        CP16(d + 0*ASZ + 16, Ah + a_row_off + ldc*8 + 8);
        CP16(d + 1*ASZ +  0, Al + a_row_off + ldc*8);
        CP16(d + 1*ASZ + 16, Al + a_row_off + ldc*8 + 8);
        CP16(d + 2*ASZ +  0, Bh + b_row_off + ldc*8);
        CP16(d + 2*ASZ + 16, Bh + b_row_off + ldc*8 + 8);
        CP16(d + 3*ASZ +  0, Bl + b_row_off + ldc*8);
        CP16(d + 3*ASZ + 16, Bl + b_row_off + ldc*8 + 8);
        CP_COMMIT();
    }
    CP_WAIT(0);
    __syncthreads();

    for (int ch = 0; ch < DM/32; ch++) {
        if (ch < DM/32 - 1) {
            const int k0 = (ch + 1) * 32;
            uint32_t d = sb + ((ch + 1) & 1) * BUFSZ + st_off;
            CP16(d + 0*ASZ +  0, Ah + a_row_off + k0 + ldc*8);
            CP16(d + 0*ASZ + 16, Ah + a_row_off + k0 + ldc*8 + 8);
            CP16(d + 1*ASZ +  0, Al + a_row_off + k0 + ldc*8);
            CP16(d + 1*ASZ + 16, Al + a_row_off + k0 + ldc*8 + 8);
            CP16(d + 2*ASZ +  0, Bh + b_row_off + k0 + ldc*8);
            CP16(d + 2*ASZ + 16, Bh + b_row_off + k0 + ldc*8 + 8);
            CP16(d + 3*ASZ +  0, Bl + b_row_off + k0 + ldc*8);
            CP16(d + 3*ASZ + 16, Bl + b_row_off + k0 + ldc*8 + 8);
            CP_COMMIT();
        }

        const uint32_t buf = sb + (ch & 1) * BUFSZ;
        #pragma unroll
        for (int ks = 0; ks < 32; ks += 16) {
            const uint32_t kadd = (uint32_t)ks * 2;
            uint32_t ah[4][4], alr[4][4];
            #pragma unroll
            for (int mt = 0; mt < 4; mt++) {
                uint32_t ao = a_lane + (uint32_t)mt * 16 * RS + kadd;
                LDSM4(ah[mt],  buf + 0*ASZ + ao);
                LDSM4(alr[mt], buf + 1*ASZ + ao);
            }
            uint32_t bh[2][4], bl[2][4];
            #pragma unroll
            for (int np = 0; np < 2; np++) {
                uint32_t bo = b_lane + (uint32_t)np * 16 * RS + kadd;
                LDSM4(bh[np], buf + 2*ASZ + bo);
                LDSM4(bl[np], buf + 3*ASZ + bo);
            }
            #pragma unroll
            for (int mt = 0; mt < 4; mt++) {
                #pragma unroll
                for (int nt = 0; nt < 4; nt++) {
                    const int np = nt >> 1, h = (nt & 1) * 2;
                    MMA16816(acc[mt*4+nt], ah[mt],  bh[np][h], bh[np][h+1]);
                    MMA16816(acc[mt*4+nt], ah[mt],  bl[np][h], bl[np][h+1]);
                    MMA16816(acc[mt*4+nt], alr[mt], bh[np][h], bh[np][h+1]);
                }
            }
        }
        if (ch < DM/32 - 1) {
            CP_WAIT(0);
            __syncthreads();
        }
    }

    // epilogue
    __nv_bfloat16 *oh = nullptr, *ol = nullptr;
    if (mode == 0) { oh = g_qh; ol = g_ql; }
    else if (mode == 1) { oh = g_kh; ol = g_kl; }
    else if (mode == 2) { oh = g_vh; ol = g_vl; }

    #pragma unroll
    for (int nt = 0; nt < 4; nt++) {
        const int n = n0 + warpN*32 + nt*8 + (l & 3)*2;
        const float bx = bias[n], by = bias[n+1];
        #pragma unroll
        for (int mt = 0; mt < 4; mt++) {
            const float* d = acc[mt*4 + nt];
            #pragma unroll
            for (int half = 0; half < 2; half++) {
                const int m = m0 + warpM*64 + mt*16 + (l >> 2) + half*8;
                float vx = (d[half*2 + 0] + bx) * ascale;
                float vy = (d[half*2 + 1] + by) * ascale;
                if (mode == 3) {
                    float2 v; v.x = vx; v.y = vy;
                    *(float2*)&outp[(size_t)m*DM + n] = v;
                } else {
                    const int bb = m >> 11, s = m & (SS-1);
                    const int hh = n >> 6, dd = n & 63;
                    size_t o = (size_t)((bb*NH + hh)*SS + s)*HD + dd;
                    __nv_bfloat16 hx = __float2bfloat16(vx);
                    __nv_bfloat16 hy = __float2bfloat16(vy);
                    __nv_bfloat16 lx = __float2bfloat16(vx - __bfloat162float(hx));
                    __nv_bfloat16 ly = __float2bfloat16(vy - __bfloat162float(hy));
                    *(__nv_bfloat162*)(oh + o) = __nv_bfloat162(hx, hy);
                    *(__nv_bfloat162*)(ol + o) = __nv_bfloat162(lx, ly);
                }
            }
        }
    }
}

// ---------------------------------------------------------------------------
// Flash attention on tensor cores (split-bf16, online softmax).
// Block: 128 queries x one (b,h); 256 threads = 8 warps, warp = 16 q rows.
// KV tile 64, double-buffered cp.async. Scores scale folded into Q (1/32).
// Writes normalized O as split-bf16 directly into g_ah/g_al ([B,S,D] layout).
// ---------------------------------------------------------------------------
#define FRS 144                    // flash smem row stride bytes (72 bf16)
#define QTILE (128*FRS)            // 18432
#define KVTILE (64*FRS)            // 9216
#define KVSTAGE (4*KVTILE)         // KH KL VH VL = 36864
#define FL_SMEM (2*QTILE + 2*KVSTAGE)   // 110592

__device__ __forceinline__ void kv_stage(uint32_t dstbase, size_t bhoff, int kv0, int t) {
    const int row = t >> 3;     // 0..31
    const int ch  = t & 7;
    #pragma unroll
    for (int half = 0; half < 2; half++) {
        const int r = row + half*32;
        const uint32_t dro = (uint32_t)r*FRS + (uint32_t)ch*16;
        const size_t sro = bhoff + (size_t)(kv0 + r)*HD + ch*8;
        CP16(dstbase + 0*KVTILE + dro, g_kh + sro);
        CP16(dstbase + 1*KVTILE + dro, g_kl + sro);
        CP16(dstbase + 2*KVTILE + dro, g_vh + sro);
        CP16(dstbase + 3*KVTILE + dro, g_vl + sro);
    }
}

__global__ void __launch_bounds__(256, 1) flash_mma() {
    extern __shared__ char fsm[];
    const uint32_t sb = smem_u32(fsm);
    const int bh = blockIdx.y;
    const int q0 = blockIdx.x * 128;
    const size_t bhoff = (size_t)bh * SS * HD;
    const int t = threadIdx.x, wid = t >> 5, l = t & 31;
    const int q = l >> 3, lr = l & 7;
    const int wq0 = wid * 16;

    // stage Q (hi+lo) and KV stage 0
    {
        const int ch = t & 7;
        #pragma unroll
        for (int p = 0; p < 4; p++) {
            const int row = (t >> 3) + p*32;
            const uint32_t dro = (uint32_t)row*FRS + (uint32_t)ch*16;
            const size_t sro = bhoff + (size_t)(q0 + row)*HD + ch*8;
            CP16(sb + dro, g_qh + sro);
            CP16(sb + QTILE + dro, g_ql + sro);
        }
    }
    kv_stage(sb + 2*QTILE, bhoff, 0, t);
    CP_COMMIT();
    CP_WAIT(0);
    __syncthreads();

    // Q fragments (held in registers for the whole kernel)
    uint32_t qhf[4][4], qlf[4][4];
    #pragma unroll
    for (int kt = 0; kt < 4; kt++) {
        uint32_t ad = sb + (uint32_t)(wq0 + (q & 1)*8 + lr)*FRS + (uint32_t)(q >> 1)*16 + kt*32;
        LDSM4(qhf[kt], ad);
        LDSM4(qlf[kt], ad + QTILE);
    }

    float oacc[8][4];
    #pragma unroll
    for (int i = 0; i < 8; i++)
        #pragma unroll
        for (int j = 0; j < 4; j++) oacc[i][j] = 0.f;
    float mprev0 = -1e30f, mprev1 = -1e30f, lsum0 = 0.f, lsum1 = 0.f;

    for (int ti = 0; ti < SS/64; ti++) {
        if (ti < SS/64 - 1) {
            kv_stage(sb + 2*QTILE + ((ti+1) & 1)*KVSTAGE, bhoff, (ti+1)*64, t);
            CP_COMMIT();
        }
        const uint32_t kb = sb + 2*QTILE + (ti & 1)*KVSTAGE;

        // S = Qh Kh + Qh Kl + Ql Kh  (scores already scaled via Q)
        float sacc[8][4];
        #pragma unroll
        for (int i = 0; i < 8; i++)
            #pragma unroll
            for (int j = 0; j < 4; j++) sacc[i][j] = 0.f;

        #pragma unroll
        for (int kt = 0; kt < 4; kt++) {
            uint32_t khf[4][4], klf[4][4];
            #pragma unroll
            for (int np = 0; np < 4; np++) {
                uint32_t ba = kb + (uint32_t)(np*16 + (q >> 1)*8 + lr)*FRS + kt*32 + (q & 1)*16;
                LDSM4(khf[np], ba);
                LDSM4(klf[np], ba + KVTILE);
            }
            #pragma unroll
            for (int nt = 0; nt < 8; nt++) {
                const int np = nt >> 1, h = (nt & 1)*2;
                MMA16816(sacc[nt], qhf[kt], khf[np][h], khf[np][h+1]);
            }
            #pragma unroll
            for (int nt = 0; nt < 8; nt++) {
                const int np = nt >> 1, h = (nt & 1)*2;
                MMA16816(sacc[nt], qhf[kt], klf[np][h], klf[np][h+1]);
            }
            #pragma unroll
            for (int nt = 0; nt < 8; nt++) {
                const int np = nt >> 1, h = (nt & 1)*2;
                MMA16816(sacc[nt], qlf[kt], khf[np][h], khf[np][h+1]);
            }
        }

        // online softmax (rows r0 = l>>2, r1 = r0+8 within warp tile)
        float m0 = sacc[0][0], m1 = sacc[0][2];
        #pragma unroll
        for (int nt = 0; nt < 8; nt++) {
            m0 = fmaxf(m0, fmaxf(sacc[nt][0], sacc[nt][1]));
            m1 = fmaxf(m1, fmaxf(sacc[nt][2], sacc[nt][3]));
        }
        m0 = fmaxf(m0, __shfl_xor_sync(0xffffffffu, m0, 1));
        m0 = fmaxf(m0, __shfl_xor_sync(0xffffffffu, m0, 2));
        m1 = fmaxf(m1, __shfl_xor_sync(0xffffffffu, m1, 1));
        m1 = fmaxf(m1, __shfl_xor_sync(0xffffffffu, m1, 2));

        const float mn0 = fmaxf(mprev0, m0);
        const float mn1 = fmaxf(mprev1, m1);
        const float a0 = __expf(mprev0 - mn0);
        const float a1 = __expf(mprev1 - mn1);
        mprev0 = mn0; mprev1 = mn1;

        float rs0 = 0.f, rs1 = 0.f;
        #pragma unroll
        for (int nt = 0; nt < 8; nt++) {
            sacc[nt][0] = __expf(sacc[nt][0] - mn0);
            sacc[nt][1] = __expf(sacc[nt][1] - mn0);
            sacc[nt][2] = __expf(sacc[nt][2] - mn1);
            sacc[nt][3] = __expf(sacc[nt][3] - mn1);
            rs0 += sacc[nt][0] + sacc[nt][1];
            rs1 += sacc[nt][2] + sacc[nt][3];
        }
        rs0 += __shfl_xor_sync(0xffffffffu, rs0, 1);
        rs0 += __shfl_xor_sync(0xffffffffu, rs0, 2);
        rs1 += __shfl_xor_sync(0xffffffffu, rs1, 1);
        rs1 += __shfl_xor_sync(0xffffffffu, rs1, 2);
        lsum0 = lsum0*a0 + rs0;
        lsum1 = lsum1*a1 + rs1;
        #pragma unroll
        for (int nj = 0; nj < 8; nj++) {
            oacc[nj][0] *= a0; oacc[nj][1] *= a0;
            oacc[nj][2] *= a1; oacc[nj][3] *= a1;
        }

        // O += (Ph + Pl) @ Vh + Ph @ Vl
        #pragma unroll
        for (int kt = 0; kt < 4; kt++) {
            uint32_t ph[4], pl[4];
            #pragma unroll
            for (int e = 0; e < 4; e++) {
                const float* s0 = sacc[2*kt + (e >> 1)];
                const float x0 = s0[(e & 1)*2], x1 = s0[(e & 1)*2 + 1];
                ph[e] = pack_bf(x1, x0);
                pl[e] = pack_bf(x1 - bf_round(x1), x0 - bf_round(x0));
            }
            uint32_t vhf[4][4], vlf[4][4];
            #pragma unroll
            for (int g = 0; g < 4; g++) {
                uint32_t va = kb + 2*KVTILE + (uint32_t)(kt*16 + (q & 1)*8 + lr)*FRS
                              + (uint32_t)(2*g + (q >> 1))*16;
                LDSM4T(vhf[g], va);
                LDSM4T(vlf[g], va + KVTILE);
            }
            #pragma unroll
            for (int nj = 0; nj < 8; nj++) {
                const int g = nj >> 1, o = (nj & 1)*2;
                MMA16816(oacc[nj], ph, vhf[g][o], vhf[g][o+1]);
            }
            #pragma unroll
            for (int nj = 0; nj < 8; nj++) {
                const int g = nj >> 1, o = (nj & 1)*2;
                MMA16816(oacc[nj], ph, vlf[g][o], vlf[g][o+1]);
            }
            #pragma unroll
            for (int nj = 0; nj < 8; nj++) {
                const int g = nj >> 1, o = (nj & 1)*2;
                MMA16816(oacc[nj], pl, vhf[g][o], vhf[g][o+1]);
            }
        }

        if (ti < SS/64 - 1) {
            CP_WAIT(0);
            __syncthreads();
        }
    }

    // epilogue: normalize, split to bf16, write to g_ah/g_al in [B,S,D]
    const float inv0 = 1.0f / lsum0;
    const float inv1 = 1.0f / lsum1;
    const int r0 = q0 + wq0 + (l >> 2);
    const int bb = bh >> 4, hh = bh & 15;
    #pragma unroll
    for (int nj = 0; nj < 8; nj++) {
        const int col = hh*HD + nj*8 + (l & 3)*2;
        {
            const float e0 = oacc[nj][0]*inv0, e1 = oacc[nj][1]*inv0;
            __nv_bfloat16 h0 = __float2bfloat16(e0), h1 = __float2bfloat16(e1);
            __nv_bfloat16 l0 = __float2bfloat16(e0 - __bfloat162float(h0));
            __nv_bfloat16 l1 = __float2bfloat16(e1 - __bfloat162float(h1));
            size_t o = (size_t)(bb*SS + r0)*DM + col;
            *(__nv_bfloat162*)(g_ah + o) = __nv_bfloat162(h0, h1);
            *(__nv_bfloat162*)(g_al + o) = __nv_bfloat162(l0, l1);
        }
        {
            const float e0 = oacc[nj][2]*inv1, e1 = oacc[nj][3]*inv1;
            __nv_bfloat16 h0 = __float2bfloat16(e0), h1 = __float2bfloat16(e1);
            __nv_bfloat16 l0 = __float2bfloat16(e0 - __bfloat162float(h0));
            __nv_bfloat16 l1 = __float2bfloat16(e1 - __bfloat162float(h1));
            size_t o = (size_t)(bb*SS + r0 + 8)*DM + col;
            *(__nv_bfloat162*)(g_ah + o) = __nv_bfloat162(h0, h1);
            *(__nv_bfloat162*)(g_al + o) = __nv_bfloat162(l0, l1);
        }
    }
}

// ---------------------------------------------------------------------------
extern "C" void kernel_launch(void* const* d_in, const int* in_sizes, int n_in,
                              void* d_out, int out_size) {
    const float* x     = (const float*)d_in[0];
    const float* rel   = (const float*)d_in[1];
    const float* alpha = (const float*)d_in[2];
    const float* Wq    = (const float*)d_in[3];
    const float* bq    = (const float*)d_in[4];
    const float* Wk    = (const float*)d_in[5];
    const float* bk    = (const float*)d_in[6];
    const float* Wv    = (const float*)d_in[7];
    const float* bv    = (const float*)d_in[8];
    const float* Wo    = (const float*)d_in[9];
    const float* bo    = (const float*)d_in[10];
    float* out = (float*)d_out;

    cudaFuncSetAttribute(gemm_mma, cudaFuncAttributeMaxDynamicSharedMemorySize, GEMM_SMEM);
    cudaFuncSetAttribute(flash_mma, cudaFuncAttributeMaxDynamicSharedMemorySize, FL_SMEM);

    __nv_bfloat16 *ah, *al, *wh, *wl;
    float *xpe;
    cudaGetSymbolAddress((void**)&ah,  g_ah);
    cudaGetSymbolAddress((void**)&al,  g_al);
    cudaGetSymbolAddress((void**)&wh,  g_wh);
    cudaGetSymbolAddress((void**)&wl,  g_wl);
    cudaGetSymbolAddress((void**)&xpe, g_xpe);

    pe_kernel<<<(MT*(DM/2) + 255)/256, 256>>>(x, rel, alpha);

    const int nA4 = MT*DM/4, nW4 = DM*DM/4;
    split_kernel<<<(nA4 + 255)/256, 256>>>(xpe, ah, al, nA4);

    dim3 gg(DM/128, MT/128);   // (8, 32)
    split_kernel<<<(nW4 + 255)/256, 256>>>(Wq, wh, wl, nW4);
    gemm_mma<<<gg, 256, GEMM_SMEM>>>(ah, al, bq, nullptr, 0.03125f, 0);
    split_kernel<<<(nW4 + 255)/256, 256>>>(Wk, wh, wl, nW4);
    gemm_mma<<<gg, 256, GEMM_SMEM>>>(ah, al, bk, nullptr, 1.0f, 1);
    split_kernel<<<(nW4 + 255)/256, 256>>>(Wv, wh, wl, nW4);
    gemm_mma<<<gg, 256, GEMM_SMEM>>>(ah, al, bv, nullptr, 1.0f, 2);

    flash_mma<<<dim3(SS/128, BB*NH), 256, FL_SMEM>>>();

    split_kernel<<<(nW4 + 255)/256, 256>>>(Wo, wh, wl, nW4);
    gemm_mma<<<gg, 256, GEMM_SMEM>>>(ah, al, bo, out, 1.0f, 3);
}